// round 2
// baseline (speedup 1.0000x reference)
#include <cuda_runtime.h>
#include <mma.h>
using namespace nvcuda;

// Problem dims
constexpr int kB = 64;      // batch
constexpr int kT = 512;     // seq len
constexpr int kE = 512;     // embed
constexpr int kH = 1024;    // hidden
constexpr int kBT = kB * kT;           // 32768
constexpr int k3H = 3 * kH;            // 3072
constexpr size_t kXPSZ = (size_t)kBT * k3H;       // per-dir xp elements
constexpr size_t kOUTSZ = (size_t)kBT * 2 * kH;   // outputs elements

// Scratch (device globals are the sanctioned scratch mechanism)
__device__ float g_emb[(size_t)kBT * kE];   // 64 MB
__device__ float g_xp[2 * kXPSZ];           // 805 MB, fwd then bwd
__device__ float g_h[2][2][kB * kH];        // [parity][dir][B*H]

// ---------------------------------------------------------------------------
__global__ void zero_h_kernel() {
    int idx = blockIdx.x * blockDim.x + threadIdx.x;  // 262144 total
    ((float*)g_h)[idx] = 0.0f;
}

// emb[m, :] = embed_W[seqs[m], :]
__global__ void gather_kernel(const int* __restrict__ seqs,
                              const float* __restrict__ embW) {
    int m = blockIdx.x;
    int t4 = threadIdx.x;  // 128 threads, E/4 float4 per row
    int row = seqs[m];
    reinterpret_cast<float4*>(g_emb)[(size_t)m * (kE / 4) + t4] =
        reinterpret_cast<const float4*>(embW)[(size_t)row * (kE / 4) + t4];
}

// ---------------------------------------------------------------------------
// xp = emb @ W_ih^T + b_ih for both directions.
// Block tile M=128, N=64, K-chunk 16. 8 warps (4x2), warp tile 32x32.
// tf32 wmma m16n16k8, fp32 accumulate.
__global__ void xp_gemm_kernel(const float* __restrict__ Wf,
                               const float* __restrict__ Wb,
                               const float* __restrict__ bf,
                               const float* __restrict__ bb) {
    constexpr int BM = 128, BN = 64, BK = 16, BKP = 20;
    __shared__ float As[BM][BKP];
    __shared__ float Bs[BN][BKP];
    __shared__ float Cs[8][32][32];

    int dir = blockIdx.z;
    const float* W = dir ? Wb : Wf;
    const float* bias = dir ? bb : bf;
    float* xp = g_xp + (size_t)dir * kXPSZ;

    int m0 = blockIdx.y * BM, n0 = blockIdx.x * BN;
    int tid = threadIdx.x, wid = tid >> 5, lane = tid & 31;
    int wm = wid >> 1, wn = wid & 1;

    wmma::fragment<wmma::accumulator, 16, 16, 8, float> acc[2][2];
#pragma unroll
    for (int i = 0; i < 2; i++)
#pragma unroll
        for (int j = 0; j < 2; j++) wmma::fill_fragment(acc[i][j], 0.0f);

    for (int k0 = 0; k0 < kE; k0 += BK) {
        // load A tile: 128x16 floats = 512 float4, 2 per thread
#pragma unroll
        for (int it = 0; it < 2; it++) {
            int i = tid + it * 256;
            int r = i >> 2, c4 = i & 3;
            float4 v = *reinterpret_cast<const float4*>(
                &g_emb[(size_t)(m0 + r) * kE + k0 + c4 * 4]);
            *reinterpret_cast<float4*>(&As[r][c4 * 4]) = v;
        }
        // load B tile: 64x16 floats = 256 float4, 1 per thread
        {
            int r = tid >> 2, c4 = tid & 3;
            float4 v = *reinterpret_cast<const float4*>(
                &W[(size_t)(n0 + r) * kE + k0 + c4 * 4]);
            *reinterpret_cast<float4*>(&Bs[r][c4 * 4]) = v;
        }
        __syncthreads();
#pragma unroll
        for (int kk = 0; kk < BK; kk += 8) {
            wmma::fragment<wmma::matrix_a, 16, 16, 8, wmma::precision::tf32,
                           wmma::row_major> a[2];
            wmma::fragment<wmma::matrix_b, 16, 16, 8, wmma::precision::tf32,
                           wmma::col_major> b[2];
            wmma::load_matrix_sync(a[0], &As[wm * 32][kk], BKP);
            wmma::load_matrix_sync(a[1], &As[wm * 32 + 16][kk], BKP);
            wmma::load_matrix_sync(b[0], &Bs[wn * 32][kk], BKP);
            wmma::load_matrix_sync(b[1], &Bs[wn * 32 + 16][kk], BKP);
#pragma unroll
            for (int i = 0; i < 2; i++) {
#pragma unroll
                for (int e = 0; e < a[i].num_elements; e++)
                    a[i].x[e] = wmma::__float_to_tf32(a[i].x[e]);
#pragma unroll
                for (int e = 0; e < b[i].num_elements; e++)
                    b[i].x[e] = wmma::__float_to_tf32(b[i].x[e]);
            }
#pragma unroll
            for (int i = 0; i < 2; i++)
#pragma unroll
                for (int j = 0; j < 2; j++)
                    wmma::mma_sync(acc[i][j], a[i], b[j], acc[i][j]);
        }
        __syncthreads();
    }
    // epilogue: stage per-warp C in smem, add bias, write coalesced
#pragma unroll
    for (int i = 0; i < 2; i++)
#pragma unroll
        for (int j = 0; j < 2; j++)
            wmma::store_matrix_sync(&Cs[wid][i * 16][j * 16], acc[i][j], 32,
                                    wmma::mem_row_major);
    __syncwarp();
    int gm = m0 + wm * 32, gn = n0 + wn * 32;
    float bv = bias[gn + lane];
#pragma unroll
    for (int r = 0; r < 32; r++) {
        xp[(size_t)(gm + r) * k3H + gn + lane] = Cs[wid][r][lane] + bv;
    }
}

// ---------------------------------------------------------------------------
// One GRU time step, both directions. 128 blocks: 64 per dir, each owns 16
// hidden columns j0..j0+15 and computes the 3 gate columns {j, H+j, 2H+j}.
// GEMM: M=64(batch) x N=48(3 gates x 16) x K=1024, 12 warps (4 m-tiles x 3 gates).
__global__ void step_kernel(const float* __restrict__ Whf,
                            const float* __restrict__ Whb,
                            const float* __restrict__ bhf,
                            const float* __restrict__ bhb,
                            float* __restrict__ out, int s, int parity) {
    constexpr int BK = 16, BKP = 20;
    __shared__ float As[kB][BKP];
    __shared__ float Bs[48][BKP];
    __shared__ float Cs[kB][48];

    int bx = blockIdx.x;
    int dir = bx >> 6;
    int j0 = (bx & 63) * 16;
    const float* W = dir ? Whb : Whf;
    const float* bhh = dir ? bhb : bhf;
    const float* hprev = g_h[parity][dir];
    float* hnext = g_h[parity ^ 1][dir];
    const float* xp = g_xp + (size_t)dir * kXPSZ;
    int t_idx = dir ? (kT - 1 - s) : s;

    int tid = threadIdx.x, wid = tid >> 5;
    int g = wid >> 2;      // gate 0..2
    int mt = wid & 3;      // m-tile 0..3

    wmma::fragment<wmma::accumulator, 16, 16, 8, float> acc;
    wmma::fill_fragment(acc, 0.0f);

    for (int k0 = 0; k0 < kH; k0 += BK) {
        if (tid < 256) {  // A: 64x16 = 256 float4
            int r = tid >> 2, c4 = tid & 3;
            *reinterpret_cast<float4*>(&As[r][c4 * 4]) =
                *reinterpret_cast<const float4*>(
                    &hprev[(size_t)r * kH + k0 + c4 * 4]);
        }
        if (tid < 192) {  // B: 48x16 = 192 float4
            int r = tid >> 2, c4 = tid & 3;
            int wrow = (r >> 4) * kH + j0 + (r & 15);
            *reinterpret_cast<float4*>(&Bs[r][c4 * 4]) =
                *reinterpret_cast<const float4*>(
                    &W[(size_t)wrow * kH + k0 + c4 * 4]);
        }
        __syncthreads();
#pragma unroll
        for (int kk = 0; kk < BK; kk += 8) {
            wmma::fragment<wmma::matrix_a, 16, 16, 8, wmma::precision::tf32,
                           wmma::row_major> a;
            wmma::fragment<wmma::matrix_b, 16, 16, 8, wmma::precision::tf32,
                           wmma::col_major> b;
            wmma::load_matrix_sync(a, &As[mt * 16][kk], BKP);
            wmma::load_matrix_sync(b, &Bs[g * 16][kk], BKP);
#pragma unroll
            for (int e = 0; e < a.num_elements; e++)
                a.x[e] = wmma::__float_to_tf32(a.x[e]);
#pragma unroll
            for (int e = 0; e < b.num_elements; e++)
                b.x[e] = wmma::__float_to_tf32(b.x[e]);
            wmma::mma_sync(acc, a, b, acc);
        }
        __syncthreads();
    }
    wmma::store_matrix_sync(&Cs[mt * 16][g * 16], acc, 48, wmma::mem_row_major);
    __syncthreads();

    // gate fusion + h update + output write
    for (int idx = tid; idx < kB * 16; idx += 384) {
        int b = idx >> 4, jj = idx & 15, j = j0 + jj;
        size_t mrow = (size_t)(b * kT + t_idx);
        const float* xpr = xp + mrow * k3H;
        float xr = xpr[j], xz = xpr[kH + j], xn = xpr[2 * kH + j];
        float ghr = Cs[b][jj] + bhh[j];
        float ghz = Cs[b][16 + jj] + bhh[kH + j];
        float ghn = Cs[b][32 + jj] + bhh[2 * kH + j];
        float r = 1.0f / (1.0f + __expf(-(xr + ghr)));
        float z = 1.0f / (1.0f + __expf(-(xz + ghz)));
        float n = tanhf(xn + r * ghn);
        float hp = hprev[b * kH + j];
        float hv = (1.0f - z) * n + z * hp;
        hnext[b * kH + j] = hv;
        out[mrow * (2 * kH) + dir * kH + j] = hv;
    }
}

// ---------------------------------------------------------------------------
// hiddens = tanh([h_f, h_b] @ fc_W^T + fc_b). Final states live in g_h[0][*].
// Block: 8 warps, one output per warp; grid (H/8, B).
__global__ void fc_kernel(const float* __restrict__ fcW,
                          const float* __restrict__ fcb,
                          float* __restrict__ out) {
    __shared__ float hc[2 * kH];
    int b = blockIdx.y;
    int tid = threadIdx.x, wid = tid >> 5, lane = tid & 31;
    for (int i = tid; i < (2 * kH) / 4; i += 256) {
        int k = i * 4;
        float4 v;
        if (k < kH)
            v = *reinterpret_cast<const float4*>(&g_h[0][0][b * kH + k]);
        else
            v = *reinterpret_cast<const float4*>(&g_h[0][1][b * kH + k - kH]);
        *reinterpret_cast<float4*>(&hc[k]) = v;
    }
    __syncthreads();
    int o = blockIdx.x * 8 + wid;
    const float4* wr = reinterpret_cast<const float4*>(&fcW[(size_t)o * 2 * kH]);
    const float4* hr = reinterpret_cast<const float4*>(hc);
    float sum = 0.0f;
    for (int i = lane; i < (2 * kH) / 4; i += 32) {
        float4 w = wr[i], h = hr[i];
        sum += w.x * h.x + w.y * h.y + w.z * h.z + w.w * h.w;
    }
#pragma unroll
    for (int off = 16; off; off >>= 1)
        sum += __shfl_xor_sync(0xffffffff, sum, off);
    if (lane == 0) out[kOUTSZ + (size_t)b * kH + o] = tanhf(sum + fcb[o]);
}

// ---------------------------------------------------------------------------
extern "C" void kernel_launch(void* const* d_in, const int* in_sizes, int n_in,
                              void* d_out, int out_size) {
    const int* seqs      = (const int*)d_in[0];
    const float* embW    = (const float*)d_in[1];
    const float* W_ih_f  = (const float*)d_in[2];
    const float* W_hh_f  = (const float*)d_in[3];
    const float* b_ih_f  = (const float*)d_in[4];
    const float* b_hh_f  = (const float*)d_in[5];
    const float* W_ih_b  = (const float*)d_in[6];
    const float* W_hh_b  = (const float*)d_in[7];
    const float* b_ih_b  = (const float*)d_in[8];
    const float* b_hh_b  = (const float*)d_in[9];
    const float* fc_W    = (const float*)d_in[10];
    const float* fc_b    = (const float*)d_in[11];
    float* out = (float*)d_out;

    zero_h_kernel<<<1024, 256>>>();
    gather_kernel<<<kBT, 128>>>(seqs, embW);
    xp_gemm_kernel<<<dim3(48, 256, 2), 256>>>(W_ih_f, W_ih_b, b_ih_f, b_ih_b);
    for (int s = 0; s < kT; s++)
        step_kernel<<<128, 384>>>(W_hh_f, W_hh_b, b_hh_f, b_hh_b, out, s, s & 1);
    fc_kernel<<<dim3(kH / 8, kB), 256>>>(fc_W, fc_b, out);
}